// round 1
// baseline (speedup 1.0000x reference)
#include <cuda_runtime.h>
#include <cstdint>

#define LDIM 256
#define CDIM 128
#define NH 4
#define HDIM 32
#define NROWS (LDIM*LDIM)        // 65536
#define QKVN 384
#define SQRT32 5.656854249492380f

// ---------------- scratch (static device globals; no allocation) ----------------
__device__ float g_zn  [(size_t)NROWS * CDIM];   // LN output, tf32-rounded
__device__ float g_qkv [(size_t)NROWS * QKVN];   // qkv, tf32-rounded
__device__ float g_gate[(size_t)NROWS * CDIM];   // sigmoid gate, fp32
__device__ float g_bias[(size_t)NROWS * NH];     // pair bias, fp32
__device__ float g_attn[(size_t)NROWS * CDIM];   // attention output, fp32

// ---------------- helpers ----------------
__device__ __forceinline__ unsigned f2tf(float f) {
    unsigned r;
    asm("cvt.rna.tf32.f32 %0, %1;" : "=r"(r) : "f"(f));
    return r;
}
__device__ __forceinline__ float f2tff(float f) { return __uint_as_float(f2tf(f)); }
__device__ __forceinline__ unsigned fu(float f) { return __float_as_uint(f); }

__device__ __forceinline__ void mma_tf32(float c[4], const unsigned a[4], const unsigned b[2]) {
    asm volatile(
        "mma.sync.aligned.m16n8k8.row.col.f32.tf32.tf32.f32 "
        "{%0,%1,%2,%3},{%4,%5,%6,%7},{%8,%9},{%0,%1,%2,%3};"
        : "+f"(c[0]), "+f"(c[1]), "+f"(c[2]), "+f"(c[3])
        : "r"(a[0]), "r"(a[1]), "r"(a[2]), "r"(a[3]), "r"(b[0]), "r"(b[1]));
}

// ---------------- kernel 1: LayerNorm + pair bias ----------------
// one warp per row (128 features). Also computes bias = zn @ w_pair (128x4).
__global__ __launch_bounds__(256) void ln_kernel(
    const float* __restrict__ z, const float* __restrict__ lng,
    const float* __restrict__ lnb, const float* __restrict__ wpair)
{
    int warp = threadIdx.x >> 5, lane = threadIdx.x & 31;
    size_t row = (size_t)blockIdx.x * 8 + warp;

    float4 v = *(const float4*)(z + row * CDIM + lane * 4);
    float s  = v.x + v.y + v.z + v.w;
    float ss = v.x*v.x + v.y*v.y + v.z*v.z + v.w*v.w;
    #pragma unroll
    for (int o = 16; o; o >>= 1) {
        s  += __shfl_xor_sync(0xffffffffu, s,  o);
        ss += __shfl_xor_sync(0xffffffffu, ss, o);
    }
    float mu  = s * (1.0f / CDIM);
    float var = ss * (1.0f / CDIM) - mu * mu;
    float rstd = rsqrtf(var + 1e-5f);

    float4 gg = *(const float4*)(lng + lane * 4);
    float4 bb = *(const float4*)(lnb + lane * 4);
    float zn[4];
    zn[0] = (v.x - mu) * rstd * gg.x + bb.x;
    zn[1] = (v.y - mu) * rstd * gg.y + bb.y;
    zn[2] = (v.z - mu) * rstd * gg.z + bb.z;
    zn[3] = (v.w - mu) * rstd * gg.w + bb.w;

    // pair bias: bias[h] = sum_c zn[c] * wpair[c*4+h]
    float bh[4] = {0.f, 0.f, 0.f, 0.f};
    #pragma unroll
    for (int k = 0; k < 4; k++) {
        float4 w = *(const float4*)(wpair + (size_t)(lane * 4 + k) * NH);
        bh[0] += zn[k] * w.x; bh[1] += zn[k] * w.y;
        bh[2] += zn[k] * w.z; bh[3] += zn[k] * w.w;
    }
    #pragma unroll
    for (int o = 16; o; o >>= 1) {
        bh[0] += __shfl_xor_sync(0xffffffffu, bh[0], o);
        bh[1] += __shfl_xor_sync(0xffffffffu, bh[1], o);
        bh[2] += __shfl_xor_sync(0xffffffffu, bh[2], o);
        bh[3] += __shfl_xor_sync(0xffffffffu, bh[3], o);
    }
    if (lane == 0)
        *(float4*)(g_bias + row * NH) = make_float4(bh[0], bh[1], bh[2], bh[3]);

    float4 o4 = make_float4(f2tff(zn[0]), f2tff(zn[1]), f2tff(zn[2]), f2tff(zn[3]));
    *(float4*)(g_zn + row * CDIM + lane * 4) = o4;
}

// ---------------- kernel 2: GEMM  zn @ [w_qkv | w_gate] ----------------
// Block: 128x128 tile, K=128 full in smem. 8 warps, warp tile 32x64 (2x8 m16n8 tiles).
#define GEMM_SMEM_FLOATS (2 * 128 * 132)
__global__ __launch_bounds__(256) void gemm_qkv_gate(
    const float* __restrict__ wqkv, const float* __restrict__ wgate,
    const float* __restrict__ bgate)
{
    extern __shared__ float sm[];
    float* As = sm;             // [128][132]
    float* Bs = sm + 128 * 132; // [128][132]  (k, n)
    int tid = threadIdx.x;
    int m0 = blockIdx.x * 128, nt = blockIdx.y;
    int rb = tid >> 5, c4 = tid & 31;

    #pragma unroll
    for (int p = 0; p < 16; p++) {
        int r = p * 8 + rb;
        *(float4*)(As + r * 132 + c4 * 4) =
            *(const float4*)(g_zn + (size_t)(m0 + r) * CDIM + c4 * 4);
    }
    #pragma unroll
    for (int p = 0; p < 16; p++) {
        int k = p * 8 + rb;
        float4 w;
        if (nt < 3) w = *(const float4*)(wqkv + (size_t)k * QKVN + nt * 128 + c4 * 4);
        else        w = *(const float4*)(wgate + (size_t)k * CDIM + c4 * 4);
        w.x = f2tff(w.x); w.y = f2tff(w.y); w.z = f2tff(w.z); w.w = f2tff(w.w);
        *(float4*)(Bs + k * 132 + c4 * 4) = w;
    }
    __syncthreads();

    int warp = tid >> 5, lane = tid & 31;
    int lr = lane >> 2, lc = lane & 3;
    int wm = warp & 3, wn = warp >> 2;

    float acc[2][8][4];
    #pragma unroll
    for (int mi = 0; mi < 2; mi++)
        #pragma unroll
        for (int ni = 0; ni < 8; ni++)
            acc[mi][ni][0] = acc[mi][ni][1] = acc[mi][ni][2] = acc[mi][ni][3] = 0.f;

    #pragma unroll
    for (int ks = 0; ks < 16; ks++) {
        int k0 = ks * 8;
        unsigned a[2][4], bf[8][2];
        #pragma unroll
        for (int mi = 0; mi < 2; mi++) {
            int r = wm * 32 + mi * 16 + lr;
            a[mi][0] = fu(As[r * 132 + k0 + lc]);
            a[mi][1] = fu(As[(r + 8) * 132 + k0 + lc]);
            a[mi][2] = fu(As[r * 132 + k0 + 4 + lc]);
            a[mi][3] = fu(As[(r + 8) * 132 + k0 + 4 + lc]);
        }
        #pragma unroll
        for (int ni = 0; ni < 8; ni++) {
            int n = wn * 64 + ni * 8 + lr;
            bf[ni][0] = fu(Bs[(k0 + lc) * 132 + n]);
            bf[ni][1] = fu(Bs[(k0 + 4 + lc) * 132 + n]);
        }
        #pragma unroll
        for (int mi = 0; mi < 2; mi++)
            #pragma unroll
            for (int ni = 0; ni < 8; ni++)
                mma_tf32(acc[mi][ni], a[mi], bf[ni]);
    }

    #pragma unroll
    for (int mi = 0; mi < 2; mi++) {
        #pragma unroll
        for (int ni = 0; ni < 8; ni++) {
            int gr = m0 + wm * 32 + mi * 16 + lr;
            int cn = wn * 64 + ni * 8 + lc * 2;
            if (nt < 3) {
                int gc = nt * 128 + cn;
                g_qkv[(size_t)gr * QKVN + gc]       = f2tff(acc[mi][ni][0]);
                g_qkv[(size_t)gr * QKVN + gc + 1]   = f2tff(acc[mi][ni][1]);
                g_qkv[(size_t)(gr + 8) * QKVN + gc]     = f2tff(acc[mi][ni][2]);
                g_qkv[(size_t)(gr + 8) * QKVN + gc + 1] = f2tff(acc[mi][ni][3]);
            } else {
                float b0 = bgate[cn], b1 = bgate[cn + 1];
                g_gate[(size_t)gr * CDIM + cn]       = 1.f / (1.f + __expf(-(acc[mi][ni][0] + b0)));
                g_gate[(size_t)gr * CDIM + cn + 1]   = 1.f / (1.f + __expf(-(acc[mi][ni][1] + b1)));
                g_gate[(size_t)(gr + 8) * CDIM + cn]     = 1.f / (1.f + __expf(-(acc[mi][ni][2] + b0)));
                g_gate[(size_t)(gr + 8) * CDIM + cn + 1] = 1.f / (1.f + __expf(-(acc[mi][ni][3] + b1)));
            }
        }
    }
}

// ---------------- kernel 3: attention per (r, h) ----------------
// smem: Ks[256][36], Vs[256][36], Qs[64][36], S[64][260], msk[256]
#define ATTN_SMEM_FLOATS (256*36 + 256*36 + 64*36 + 64*260 + 256)
__global__ __launch_bounds__(256) void attn_kernel(const int* __restrict__ src_mask)
{
    extern __shared__ float sm[];
    float* Ks  = sm;
    float* Vs  = Ks + 256 * 36;
    float* Qs  = Vs + 256 * 36;
    float* S   = Qs + 64 * 36;
    float* msk = S  + 64 * 260;

    int h = blockIdx.x, r = blockIdx.y;
    int tid = threadIdx.x;
    const float* base = g_qkv + (size_t)r * LDIM * QKVN;

    #pragma unroll
    for (int p = 0; p < 8; p++) {
        int lin = tid + p * 256;         // 0..2047
        int j = lin >> 3, d4 = lin & 7;
        *(float4*)(Ks + j * 36 + d4 * 4) =
            *(const float4*)(base + (size_t)j * QKVN + 128 + h * HDIM + d4 * 4);
        *(float4*)(Vs + j * 36 + d4 * 4) =
            *(const float4*)(base + (size_t)j * QKVN + 256 + h * HDIM + d4 * 4);
    }
    msk[tid] = (src_mask[tid] == 0) ? -1.f : 1.f;

    int warp = tid >> 5, lane = tid & 31;
    int lr = lane >> 2, lc = lane & 3;
    int wm = warp >> 1, wn = warp & 1;

    for (int ic = 0; ic < 4; ic++) {
        int i0 = ic * 64;
        #pragma unroll
        for (int p = 0; p < 2; p++) {
            int lin = tid + p * 256;     // 0..511
            int row = lin >> 3, d4 = lin & 7;
            *(float4*)(Qs + row * 36 + d4 * 4) =
                *(const float4*)(base + (size_t)(i0 + row) * QKVN + h * HDIM + d4 * 4);
        }
        __syncthreads();

        // ---- QK^T : S[64][256], warp = (wm m16-tile of 64 rows, wn half of 256 cols)
        float acc[16][4];
        #pragma unroll
        for (int ni = 0; ni < 16; ni++)
            acc[ni][0] = acc[ni][1] = acc[ni][2] = acc[ni][3] = 0.f;

        #pragma unroll
        for (int ks = 0; ks < 4; ks++) {
            int k0 = ks * 8;
            unsigned a[4];
            int row = wm * 16 + lr;
            a[0] = fu(Qs[row * 36 + k0 + lc]);
            a[1] = fu(Qs[(row + 8) * 36 + k0 + lc]);
            a[2] = fu(Qs[row * 36 + k0 + 4 + lc]);
            a[3] = fu(Qs[(row + 8) * 36 + k0 + 4 + lc]);
            #pragma unroll
            for (int ni = 0; ni < 16; ni++) {
                int j = wn * 128 + ni * 8 + lr;
                unsigned b[2] = { fu(Ks[j * 36 + k0 + lc]), fu(Ks[j * 36 + k0 + 4 + lc]) };
                mma_tf32(acc[ni], a, b);
            }
        }

        // epilogue: scale, +bias(i,j,h), mask, write S
        #pragma unroll
        for (int ni = 0; ni < 16; ni++) {
            int il = wm * 16 + lr;
            int j  = wn * 128 + ni * 8 + lc * 2;
            int gi0 = i0 + il, gi1 = gi0 + 8;
            float mi0 = msk[gi0], mi1 = msk[gi1];
            float mj0 = msk[j],   mj1 = msk[j + 1];
            const float* bp0 = g_bias + ((size_t)gi0 * LDIM + j) * NH + h;
            const float* bp1 = g_bias + ((size_t)gi1 * LDIM + j) * NH + h;
            float v0 = acc[ni][0] * SQRT32 + bp0[0];
            float v1 = acc[ni][1] * SQRT32 + bp0[4];
            float v2 = acc[ni][2] * SQRT32 + bp1[0];
            float v3 = acc[ni][3] * SQRT32 + bp1[4];
            if (mi0 * mj0 < 0.f) v0 = -1e-9f;
            if (mi0 * mj1 < 0.f) v1 = -1e-9f;
            if (mi1 * mj0 < 0.f) v2 = -1e-9f;
            if (mi1 * mj1 < 0.f) v3 = -1e-9f;
            S[il * 260 + j]           = v0;
            S[il * 260 + j + 1]       = v1;
            S[(il + 8) * 260 + j]     = v2;
            S[(il + 8) * 260 + j + 1] = v3;
        }
        __syncthreads();

        // ---- softmax over j (each warp owns 8 rows) ----
        #pragma unroll
        for (int rr = 0; rr < 8; rr++) {
            int row = warp * 8 + rr;
            float* Sr = S + row * 260;
            float vals[8];
            float mx = -1e30f;
            #pragma unroll
            for (int kk = 0; kk < 8; kk++) { vals[kk] = Sr[lane + kk * 32]; mx = fmaxf(mx, vals[kk]); }
            #pragma unroll
            for (int o = 16; o; o >>= 1) mx = fmaxf(mx, __shfl_xor_sync(0xffffffffu, mx, o));
            float sum = 0.f;
            #pragma unroll
            for (int kk = 0; kk < 8; kk++) { vals[kk] = __expf(vals[kk] - mx); sum += vals[kk]; }
            #pragma unroll
            for (int o = 16; o; o >>= 1) sum += __shfl_xor_sync(0xffffffffu, sum, o);
            float inv = 1.f / sum;
            #pragma unroll
            for (int kk = 0; kk < 8; kk++) Sr[lane + kk * 32] = f2tff(vals[kk] * inv);
        }
        __syncthreads();

        // ---- P @ V : out[64][32], warp = (wm rows, wn 16-col half), k = 256 ----
        float oc[2][4];
        oc[0][0]=oc[0][1]=oc[0][2]=oc[0][3]=0.f;
        oc[1][0]=oc[1][1]=oc[1][2]=oc[1][3]=0.f;
        #pragma unroll 4
        for (int ks = 0; ks < 32; ks++) {
            int k0 = ks * 8;
            unsigned a[4];
            int row = wm * 16 + lr;
            a[0] = fu(S[row * 260 + k0 + lc]);
            a[1] = fu(S[(row + 8) * 260 + k0 + lc]);
            a[2] = fu(S[row * 260 + k0 + 4 + lc]);
            a[3] = fu(S[(row + 8) * 260 + k0 + 4 + lc]);
            #pragma unroll
            for (int ni = 0; ni < 2; ni++) {
                int d = wn * 16 + ni * 8 + lr;
                unsigned b[2] = { fu(Vs[(k0 + lc) * 36 + d]), fu(Vs[(k0 + 4 + lc) * 36 + d]) };
                mma_tf32(oc[ni], a, b);
            }
        }
        #pragma unroll
        for (int ni = 0; ni < 2; ni++) {
            int il = wm * 16 + lr;
            int d  = wn * 16 + ni * 8 + lc * 2;
            size_t ro0 = ((size_t)r * LDIM + i0 + il) * CDIM + h * HDIM + d;
            size_t ro1 = ((size_t)r * LDIM + i0 + il + 8) * CDIM + h * HDIM + d;
            g_attn[ro0]     = oc[ni][0];
            g_attn[ro0 + 1] = oc[ni][1];
            g_attn[ro1]     = oc[ni][2];
            g_attn[ro1 + 1] = oc[ni][3];
        }
        __syncthreads();
    }
}

// ---------------- kernel 4: (gate * attn) @ w_out + b_out ----------------
__global__ __launch_bounds__(256) void gemm_out_kernel(
    const float* __restrict__ wout, const float* __restrict__ bout,
    float* __restrict__ out)
{
    extern __shared__ float sm[];
    float* As = sm;
    float* Bs = sm + 128 * 132;
    int tid = threadIdx.x;
    int m0 = blockIdx.x * 128;
    int rb = tid >> 5, c4 = tid & 31;

    #pragma unroll
    for (int p = 0; p < 16; p++) {
        int r = p * 8 + rb;
        float4 gte = *(const float4*)(g_gate + (size_t)(m0 + r) * CDIM + c4 * 4);
        float4 att = *(const float4*)(g_attn + (size_t)(m0 + r) * CDIM + c4 * 4);
        float4 a;
        a.x = f2tff(gte.x * att.x); a.y = f2tff(gte.y * att.y);
        a.z = f2tff(gte.z * att.z); a.w = f2tff(gte.w * att.w);
        *(float4*)(As + r * 132 + c4 * 4) = a;
    }
    #pragma unroll
    for (int p = 0; p < 16; p++) {
        int k = p * 8 + rb;
        float4 w = *(const float4*)(wout + (size_t)k * CDIM + c4 * 4);
        w.x = f2tff(w.x); w.y = f2tff(w.y); w.z = f2tff(w.z); w.w = f2tff(w.w);
        *(float4*)(Bs + k * 132 + c4 * 4) = w;
    }
    __syncthreads();

    int warp = tid >> 5, lane = tid & 31;
    int lr = lane >> 2, lc = lane & 3;
    int wm = warp & 3, wn = warp >> 2;

    float acc[2][8][4];
    #pragma unroll
    for (int mi = 0; mi < 2; mi++)
        #pragma unroll
        for (int ni = 0; ni < 8; ni++)
            acc[mi][ni][0] = acc[mi][ni][1] = acc[mi][ni][2] = acc[mi][ni][3] = 0.f;

    #pragma unroll
    for (int ks = 0; ks < 16; ks++) {
        int k0 = ks * 8;
        unsigned a[2][4], bf[8][2];
        #pragma unroll
        for (int mi = 0; mi < 2; mi++) {
            int r = wm * 32 + mi * 16 + lr;
            a[mi][0] = fu(As[r * 132 + k0 + lc]);
            a[mi][1] = fu(As[(r + 8) * 132 + k0 + lc]);
            a[mi][2] = fu(As[r * 132 + k0 + 4 + lc]);
            a[mi][3] = fu(As[(r + 8) * 132 + k0 + 4 + lc]);
        }
        #pragma unroll
        for (int ni = 0; ni < 8; ni++) {
            int n = wn * 64 + ni * 8 + lr;
            bf[ni][0] = fu(Bs[(k0 + lc) * 132 + n]);
            bf[ni][1] = fu(Bs[(k0 + 4 + lc) * 132 + n]);
        }
        #pragma unroll
        for (int mi = 0; mi < 2; mi++)
            #pragma unroll
            for (int ni = 0; ni < 8; ni++)
                mma_tf32(acc[mi][ni], a[mi], bf[ni]);
    }

    #pragma unroll
    for (int mi = 0; mi < 2; mi++) {
        #pragma unroll
        for (int ni = 0; ni < 8; ni++) {
            int gr = m0 + wm * 32 + mi * 16 + lr;
            int cn = wn * 64 + ni * 8 + lc * 2;
            float b0 = bout[cn], b1 = bout[cn + 1];
            out[(size_t)gr * CDIM + cn]       = acc[mi][ni][0] + b0;
            out[(size_t)gr * CDIM + cn + 1]   = acc[mi][ni][1] + b1;
            out[(size_t)(gr + 8) * CDIM + cn]     = acc[mi][ni][2] + b0;
            out[(size_t)(gr + 8) * CDIM + cn + 1] = acc[mi][ni][3] + b1;
        }
    }
}

// ---------------- launch ----------------
extern "C" void kernel_launch(void* const* d_in, const int* in_sizes, int n_in,
                              void* d_out, int out_size)
{
    (void)in_sizes; (void)n_in; (void)out_size;
    const float* z        = (const float*)d_in[0];
    const int*   src_mask = (const int*)  d_in[1];
    const float* ln_g     = (const float*)d_in[2];
    const float* ln_b     = (const float*)d_in[3];
    const float* w_qkv    = (const float*)d_in[4];
    const float* w_pair   = (const float*)d_in[5];
    const float* w_gate   = (const float*)d_in[6];
    const float* b_gate   = (const float*)d_in[7];
    const float* w_out    = (const float*)d_in[8];
    const float* b_out    = (const float*)d_in[9];
    float* out = (float*)d_out;

    const int gemm_smem = GEMM_SMEM_FLOATS * 4;   // 135168 B
    const int attn_smem = ATTN_SMEM_FLOATS * 4;   // 150528 B
    cudaFuncSetAttribute(gemm_qkv_gate,  cudaFuncAttributeMaxDynamicSharedMemorySize, gemm_smem);
    cudaFuncSetAttribute(attn_kernel,    cudaFuncAttributeMaxDynamicSharedMemorySize, attn_smem);
    cudaFuncSetAttribute(gemm_out_kernel,cudaFuncAttributeMaxDynamicSharedMemorySize, gemm_smem);

    ln_kernel<<<NROWS / 8, 256>>>(z, ln_g, ln_b, w_pair);
    gemm_qkv_gate<<<dim3(NROWS / 128, 4), 256, gemm_smem>>>(w_qkv, w_gate, b_gate);
    attn_kernel<<<dim3(NH, LDIM), 256, attn_smem>>>(src_mask);
    gemm_out_kernel<<<NROWS / 128, 256, gemm_smem>>>(w_out, b_out, out);
}

// round 2
// speedup vs baseline: 1.2006x; 1.2006x over previous
#include <cuda_runtime.h>
#include <cstdint>

#define LDIM 256
#define CDIM 128
#define NH 4
#define HDIM 32
#define NROWS (LDIM*LDIM)        // 65536
#define QKVN 384
#define SQRT32 5.656854249492380f

// ---------------- scratch ----------------
__device__ float g_qkv  [(size_t)NROWS * QKVN];   // qkv, tf32-rounded (q pre-scaled by sqrt32)
__device__ float g_gate [(size_t)NROWS * CDIM];   // sigmoid gate
__device__ float g_biasT[(size_t)NH * NROWS];     // pair bias, [h][i*256+j]
__device__ float g_attn [(size_t)NROWS * CDIM];   // attention output

// ---------------- helpers ----------------
__device__ __forceinline__ unsigned f2tf(float f) {
    unsigned r;
    asm("cvt.rna.tf32.f32 %0, %1;" : "=r"(r) : "f"(f));
    return r;
}
__device__ __forceinline__ float f2tff(float f) { return __uint_as_float(f2tf(f)); }
__device__ __forceinline__ unsigned fu(float f) { return __float_as_uint(f); }

__device__ __forceinline__ void mma_tf32(float c[4], const unsigned a[4], const unsigned b[2]) {
    asm volatile(
        "mma.sync.aligned.m16n8k8.row.col.f32.tf32.tf32.f32 "
        "{%0,%1,%2,%3},{%4,%5,%6,%7},{%8,%9},{%0,%1,%2,%3};"
        : "+f"(c[0]), "+f"(c[1]), "+f"(c[2]), "+f"(c[3])
        : "r"(a[0]), "r"(a[1]), "r"(a[2]), "r"(a[3]), "r"(b[0]), "r"(b[1]));
}

// ============ kernel 1: fused LN + GEMM  zn @ [w_qkv | w_gate] + pair bias ============
// 512 threads, 16 warps, warp tile 32x32. grid (512, 4). nt 0..2 = qkv 128-col slabs, nt 3 = gate.
#define GEMM_QKV_SMEM_FLOATS (2*128*132 + 128 + 128 + 512)
__global__ __launch_bounds__(512) void gemm_qkv_gate(
    const float* __restrict__ z, const float* __restrict__ lng, const float* __restrict__ lnb,
    const float* __restrict__ wqkv, const float* __restrict__ wgate,
    const float* __restrict__ bgate, const float* __restrict__ wpair)
{
    extern __shared__ float sm[];
    float* As  = sm;                 // [128][132]
    float* Bs  = sm + 128*132;       // [128][132]
    float* gS  = Bs + 128*132;       // 128
    float* bS  = gS + 128;           // 128
    float* wpS = bS + 128;           // 512

    int tid = threadIdx.x;
    int m0 = blockIdx.x * 128, nt = blockIdx.y;

    #pragma unroll
    for (int it = 0; it < 8; it++) {
        int lin = tid + it*512;
        int r = lin >> 5, c4 = lin & 31;
        *(float4*)(As + r*132 + c4*4) =
            *(const float4*)(z + (size_t)(m0 + r)*CDIM + c4*4);
    }
    #pragma unroll
    for (int it = 0; it < 8; it++) {
        int lin = tid + it*512;
        int k = lin >> 5, c4 = lin & 31;
        float4 w;
        if (nt < 3) w = *(const float4*)(wqkv + (size_t)k*QKVN + nt*128 + c4*4);
        else        w = *(const float4*)(wgate + (size_t)k*CDIM + c4*4);
        if (nt == 0) { w.x *= SQRT32; w.y *= SQRT32; w.z *= SQRT32; w.w *= SQRT32; }
        w.x = f2tff(w.x); w.y = f2tff(w.y); w.z = f2tff(w.z); w.w = f2tff(w.w);
        *(float4*)(Bs + k*132 + c4*4) = w;
    }
    if (tid < 128) { gS[tid] = lng[tid]; bS[tid] = lnb[tid]; }
    wpS[tid] = wpair[tid];
    __syncthreads();

    // ---- LayerNorm in place (row = tid>>2, quad = tid&3, 32 elems each) ----
    {
        int row = tid >> 2, quad = tid & 3;
        float* Ar = As + row*132 + quad*32;
        float v[32];
        float s = 0.f, ss = 0.f;
        #pragma unroll
        for (int i = 0; i < 8; i++) {
            float4 t = *(float4*)(Ar + i*4);
            v[i*4] = t.x; v[i*4+1] = t.y; v[i*4+2] = t.z; v[i*4+3] = t.w;
            s  += t.x + t.y + t.z + t.w;
            ss += t.x*t.x + t.y*t.y + t.z*t.z + t.w*t.w;
        }
        s  += __shfl_xor_sync(0xffffffffu, s, 1);  s  += __shfl_xor_sync(0xffffffffu, s, 2);
        ss += __shfl_xor_sync(0xffffffffu, ss, 1); ss += __shfl_xor_sync(0xffffffffu, ss, 2);
        float mu  = s * (1.0f / CDIM);
        float var = ss * (1.0f / CDIM) - mu * mu;
        float rstd = rsqrtf(var + 1e-5f);

        float bh0 = 0.f, bh1 = 0.f, bh2 = 0.f, bh3 = 0.f;
        #pragma unroll
        for (int i = 0; i < 32; i++) {
            int c = quad*32 + i;
            float zn = (v[i] - mu) * rstd * gS[c] + bS[c];
            if (nt == 3) {
                bh0 += zn * wpS[c*4];   bh1 += zn * wpS[c*4+1];
                bh2 += zn * wpS[c*4+2]; bh3 += zn * wpS[c*4+3];
            }
            Ar[i] = f2tff(zn);
        }
        if (nt == 3) {
            bh0 += __shfl_xor_sync(0xffffffffu, bh0, 1); bh0 += __shfl_xor_sync(0xffffffffu, bh0, 2);
            bh1 += __shfl_xor_sync(0xffffffffu, bh1, 1); bh1 += __shfl_xor_sync(0xffffffffu, bh1, 2);
            bh2 += __shfl_xor_sync(0xffffffffu, bh2, 1); bh2 += __shfl_xor_sync(0xffffffffu, bh2, 2);
            bh3 += __shfl_xor_sync(0xffffffffu, bh3, 1); bh3 += __shfl_xor_sync(0xffffffffu, bh3, 2);
            if (quad == 0) {
                g_biasT[(size_t)0*NROWS + m0 + row] = bh0;
                g_biasT[(size_t)1*NROWS + m0 + row] = bh1;
                g_biasT[(size_t)2*NROWS + m0 + row] = bh2;
                g_biasT[(size_t)3*NROWS + m0 + row] = bh3;
            }
        }
    }
    __syncthreads();

    // ---- MMA: 16 warps, 4x4 layout, warp tile 32x32 ----
    int warp = tid >> 5, lane = tid & 31;
    int lr = lane >> 2, lc = lane & 3;
    int wm = warp & 3, wn = warp >> 2;

    float acc[2][4][4];
    #pragma unroll
    for (int mi = 0; mi < 2; mi++)
        #pragma unroll
        for (int ni = 0; ni < 4; ni++)
            acc[mi][ni][0] = acc[mi][ni][1] = acc[mi][ni][2] = acc[mi][ni][3] = 0.f;

    #pragma unroll
    for (int ks = 0; ks < 16; ks++) {
        int k0 = ks * 8;
        unsigned a[2][4], bf[4][2];
        #pragma unroll
        for (int mi = 0; mi < 2; mi++) {
            int r = wm*32 + mi*16 + lr;
            a[mi][0] = fu(As[r*132 + k0 + lc]);
            a[mi][1] = fu(As[(r+8)*132 + k0 + lc]);
            a[mi][2] = fu(As[r*132 + k0 + 4 + lc]);
            a[mi][3] = fu(As[(r+8)*132 + k0 + 4 + lc]);
        }
        #pragma unroll
        for (int ni = 0; ni < 4; ni++) {
            int n = wn*32 + ni*8 + lr;
            bf[ni][0] = fu(Bs[(k0 + lc)*132 + n]);
            bf[ni][1] = fu(Bs[(k0 + 4 + lc)*132 + n]);
        }
        #pragma unroll
        for (int mi = 0; mi < 2; mi++)
            #pragma unroll
            for (int ni = 0; ni < 4; ni++)
                mma_tf32(acc[mi][ni], a[mi], bf[ni]);
    }

    #pragma unroll
    for (int mi = 0; mi < 2; mi++) {
        #pragma unroll
        for (int ni = 0; ni < 4; ni++) {
            int gr = m0 + wm*32 + mi*16 + lr;
            int cn = wn*32 + ni*8 + lc*2;
            if (nt < 3) {
                int gc = nt*128 + cn;
                g_qkv[(size_t)gr * QKVN + gc]           = f2tff(acc[mi][ni][0]);
                g_qkv[(size_t)gr * QKVN + gc + 1]       = f2tff(acc[mi][ni][1]);
                g_qkv[(size_t)(gr+8) * QKVN + gc]       = f2tff(acc[mi][ni][2]);
                g_qkv[(size_t)(gr+8) * QKVN + gc + 1]   = f2tff(acc[mi][ni][3]);
            } else {
                float b0 = bgate[cn], b1 = bgate[cn+1];
                g_gate[(size_t)gr * CDIM + cn]         = 1.f/(1.f + __expf(-(acc[mi][ni][0] + b0)));
                g_gate[(size_t)gr * CDIM + cn + 1]     = 1.f/(1.f + __expf(-(acc[mi][ni][1] + b1)));
                g_gate[(size_t)(gr+8) * CDIM + cn]     = 1.f/(1.f + __expf(-(acc[mi][ni][2] + b0)));
                g_gate[(size_t)(gr+8) * CDIM + cn + 1] = 1.f/(1.f + __expf(-(acc[mi][ni][3] + b1)));
            }
        }
    }
}

// ============ kernel 2: attention per (h, r), register softmax ============
// 256 threads, 8 warps: wm = warp>>1 (16-row strip of 64-chunk), wn = warp&1 (j half of 128).
#define ATTN_SMEM_FLOATS (256*36*2 + 64*36 + 128 + 128 + 64*32 + 256)
__global__ __launch_bounds__(256, 2) void attn_kernel(const int* __restrict__ src_mask)
{
    extern __shared__ float sm[];
    float* Ks     = sm;                 // [256][36]
    float* Vs     = Ks + 256*36;        // [256][36]
    float* Qs     = Vs + 256*36;        // [64][36]
    float* redmax = Qs + 64*36;         // [2][64]
    float* redsum = redmax + 128;       // [2][64]
    float* obuf   = redsum + 128;       // [64][32]
    float* msk    = obuf + 64*32;       // [256]

    int h = blockIdx.x, r = blockIdx.y;
    int tid = threadIdx.x;
    const float* base = g_qkv + (size_t)r * LDIM * QKVN;

    #pragma unroll
    for (int p = 0; p < 8; p++) {
        int lin = tid + p*256;
        int j = lin >> 3, d4 = lin & 7;
        *(float4*)(Ks + j*36 + d4*4) =
            *(const float4*)(base + (size_t)j*QKVN + 128 + h*HDIM + d4*4);
        *(float4*)(Vs + j*36 + d4*4) =
            *(const float4*)(base + (size_t)j*QKVN + 256 + h*HDIM + d4*4);
    }
    msk[tid] = (src_mask[tid] == 0) ? -1.f : 1.f;

    int warp = tid >> 5, lane = tid & 31;
    int lr = lane >> 2, lc = lane & 3;
    int wm = warp >> 1, wn = warp & 1;
    int arow = wm*16 + lr;
    const float* biasH = g_biasT + (size_t)h * NROWS;

    int s0l = (lane & ~3) | (lc >> 1);
    int s1l = s0l + 2;
    int sel = lc & 1;

    for (int ic = 0; ic < 4; ic++) {
        int i0 = ic * 64;
        #pragma unroll
        for (int p = 0; p < 2; p++) {
            int lin = tid + p*256;
            int row = lin >> 3, d4 = lin & 7;
            *(float4*)(Qs + row*36 + d4*4) =
                *(const float4*)(base + (size_t)(i0 + row)*QKVN + h*HDIM + d4*4);
        }
        __syncthreads();

        // ---- QK^T: warp covers rows [wm*16, +16), cols [wn*128, +128) ----
        float acc[16][4];
        #pragma unroll
        for (int ni = 0; ni < 16; ni++)
            acc[ni][0] = acc[ni][1] = acc[ni][2] = acc[ni][3] = 0.f;

        #pragma unroll
        for (int ks = 0; ks < 4; ks++) {
            int k0 = ks * 8;
            unsigned a[4] = { fu(Qs[arow*36 + k0 + lc]),     fu(Qs[(arow+8)*36 + k0 + lc]),
                              fu(Qs[arow*36 + k0 + 4 + lc]), fu(Qs[(arow+8)*36 + k0 + 4 + lc]) };
            #pragma unroll
            for (int ni = 0; ni < 16; ni++) {
                int j = wn*128 + ni*8 + lr;
                unsigned b[2] = { fu(Ks[j*36 + k0 + lc]), fu(Ks[j*36 + k0 + 4 + lc]) };
                mma_tf32(acc[ni], a, b);
            }
        }

        // ---- bias + mask + row max (scale already folded into q) ----
        float mi0 = msk[i0 + arow], mi1 = msk[i0 + arow + 8];
        const float* bp0 = biasH + (size_t)(i0 + arow) * LDIM;
        const float* bp1 = bp0 + 8 * LDIM;
        float mx0 = -1e30f, mx1 = -1e30f;
        #pragma unroll
        for (int ni = 0; ni < 16; ni++) {
            int j = wn*128 + ni*8 + lc*2;
            float2 b0 = *(const float2*)(bp0 + j);
            float2 b1 = *(const float2*)(bp1 + j);
            float mj0 = msk[j], mj1 = msk[j+1];
            float v0 = acc[ni][0] + b0.x;
            float v1 = acc[ni][1] + b0.y;
            float v2 = acc[ni][2] + b1.x;
            float v3 = acc[ni][3] + b1.y;
            if (mi0*mj0 < 0.f) v0 = -1e-9f;
            if (mi0*mj1 < 0.f) v1 = -1e-9f;
            if (mi1*mj0 < 0.f) v2 = -1e-9f;
            if (mi1*mj1 < 0.f) v3 = -1e-9f;
            acc[ni][0] = v0; acc[ni][1] = v1; acc[ni][2] = v2; acc[ni][3] = v3;
            mx0 = fmaxf(mx0, fmaxf(v0, v1));
            mx1 = fmaxf(mx1, fmaxf(v2, v3));
        }
        mx0 = fmaxf(mx0, __shfl_xor_sync(0xffffffffu, mx0, 1));
        mx0 = fmaxf(mx0, __shfl_xor_sync(0xffffffffu, mx0, 2));
        mx1 = fmaxf(mx1, __shfl_xor_sync(0xffffffffu, mx1, 1));
        mx1 = fmaxf(mx1, __shfl_xor_sync(0xffffffffu, mx1, 2));
        if (lc == 0) { redmax[wn*64 + arow] = mx0; redmax[wn*64 + arow + 8] = mx1; }
        __syncthreads();
        float gm0 = fmaxf(redmax[arow],     redmax[64 + arow]);
        float gm1 = fmaxf(redmax[arow + 8], redmax[64 + arow + 8]);

        // ---- exp + row sum ----
        float sm0 = 0.f, sm1 = 0.f;
        #pragma unroll
        for (int ni = 0; ni < 16; ni++) {
            float e0 = __expf(acc[ni][0] - gm0), e1 = __expf(acc[ni][1] - gm0);
            float e2 = __expf(acc[ni][2] - gm1), e3 = __expf(acc[ni][3] - gm1);
            acc[ni][0] = e0; acc[ni][1] = e1; acc[ni][2] = e2; acc[ni][3] = e3;
            sm0 += e0 + e1; sm1 += e2 + e3;
        }
        sm0 += __shfl_xor_sync(0xffffffffu, sm0, 1);
        sm0 += __shfl_xor_sync(0xffffffffu, sm0, 2);
        sm1 += __shfl_xor_sync(0xffffffffu, sm1, 1);
        sm1 += __shfl_xor_sync(0xffffffffu, sm1, 2);
        if (lc == 0) { redsum[wn*64 + arow] = sm0; redsum[wn*64 + arow + 8] = sm1; }
        __syncthreads();
        float inv0 = 1.f / (redsum[arow]     + redsum[64 + arow]);
        float inv1 = 1.f / (redsum[arow + 8] + redsum[64 + arow + 8]);
        #pragma unroll
        for (int ni = 0; ni < 16; ni++) {
            acc[ni][0] = f2tff(acc[ni][0] * inv0);
            acc[ni][1] = f2tff(acc[ni][1] * inv0);
            acc[ni][2] = f2tff(acc[ni][2] * inv1);
            acc[ni][3] = f2tff(acc[ni][3] * inv1);
        }

        // ---- P @ V over this warp's 128 j-cols ----
        float oc[4][4];
        #pragma unroll
        for (int dt = 0; dt < 4; dt++)
            oc[dt][0] = oc[dt][1] = oc[dt][2] = oc[dt][3] = 0.f;

        #pragma unroll
        for (int ni = 0; ni < 16; ni++) {
            float t00 = __shfl_sync(0xffffffffu, acc[ni][0], s0l);
            float t01 = __shfl_sync(0xffffffffu, acc[ni][1], s0l);
            float t10 = __shfl_sync(0xffffffffu, acc[ni][2], s0l);
            float t11 = __shfl_sync(0xffffffffu, acc[ni][3], s0l);
            float u00 = __shfl_sync(0xffffffffu, acc[ni][0], s1l);
            float u01 = __shfl_sync(0xffffffffu, acc[ni][1], s1l);
            float u10 = __shfl_sync(0xffffffffu, acc[ni][2], s1l);
            float u11 = __shfl_sync(0xffffffffu, acc[ni][3], s1l);
            unsigned a[4];
            a[0] = fu(sel ? t01 : t00);
            a[1] = fu(sel ? t11 : t10);
            a[2] = fu(sel ? u01 : u00);
            a[3] = fu(sel ? u11 : u10);
            int jb = wn*128 + ni*8;
            #pragma unroll
            for (int dt = 0; dt < 4; dt++) {
                unsigned b[2] = { fu(Vs[(jb + lc)*36 + dt*8 + lr]),
                                  fu(Vs[(jb + 4 + lc)*36 + dt*8 + lr]) };
                mma_tf32(oc[dt], a, b);
            }
        }

        // ---- combine the two j-halves and store ----
        if (wn == 1) {
            #pragma unroll
            for (int dt = 0; dt < 4; dt++) {
                *(float2*)(obuf + arow*32 + dt*8 + lc*2)      = make_float2(oc[dt][0], oc[dt][1]);
                *(float2*)(obuf + (arow+8)*32 + dt*8 + lc*2)  = make_float2(oc[dt][2], oc[dt][3]);
            }
        }
        __syncthreads();
        if (wn == 0) {
            size_t ro0 = ((size_t)r*LDIM + i0 + arow) * CDIM + h*HDIM;
            size_t ro1 = ro0 + 8*CDIM;
            #pragma unroll
            for (int dt = 0; dt < 4; dt++) {
                float2 p0 = *(float2*)(obuf + arow*32 + dt*8 + lc*2);
                float2 p1 = *(float2*)(obuf + (arow+8)*32 + dt*8 + lc*2);
                *(float2*)(g_attn + ro0 + dt*8 + lc*2) = make_float2(oc[dt][0] + p0.x, oc[dt][1] + p0.y);
                *(float2*)(g_attn + ro1 + dt*8 + lc*2) = make_float2(oc[dt][2] + p1.x, oc[dt][3] + p1.y);
            }
        }
    }
}

// ============ kernel 3: (gate * attn) @ w_out + b_out ============
#define GEMM_OUT_SMEM_FLOATS (2*128*132)
__global__ __launch_bounds__(512) void gemm_out_kernel(
    const float* __restrict__ wout, const float* __restrict__ bout,
    float* __restrict__ out)
{
    extern __shared__ float sm[];
    float* As = sm;
    float* Bs = sm + 128*132;
    int tid = threadIdx.x;
    int m0 = blockIdx.x * 128;

    #pragma unroll
    for (int it = 0; it < 8; it++) {
        int lin = tid + it*512;
        int r = lin >> 5, c4 = lin & 31;
        float4 gte = *(const float4*)(g_gate + (size_t)(m0 + r)*CDIM + c4*4);
        float4 att = *(const float4*)(g_attn + (size_t)(m0 + r)*CDIM + c4*4);
        float4 a;
        a.x = f2tff(gte.x * att.x); a.y = f2tff(gte.y * att.y);
        a.z = f2tff(gte.z * att.z); a.w = f2tff(gte.w * att.w);
        *(float4*)(As + r*132 + c4*4) = a;
    }
    #pragma unroll
    for (int it = 0; it < 8; it++) {
        int lin = tid + it*512;
        int k = lin >> 5, c4 = lin & 31;
        float4 w = *(const float4*)(wout + (size_t)k*CDIM + c4*4);
        w.x = f2tff(w.x); w.y = f2tff(w.y); w.z = f2tff(w.z); w.w = f2tff(w.w);
        *(float4*)(Bs + k*132 + c4*4) = w;
    }
    __syncthreads();

    int warp = tid >> 5, lane = tid & 31;
    int lr = lane >> 2, lc = lane & 3;
    int wm = warp & 3, wn = warp >> 2;

    float acc[2][4][4];
    #pragma unroll
    for (int mi = 0; mi < 2; mi++)
        #pragma unroll
        for (int ni = 0; ni < 4; ni++)
            acc[mi][ni][0] = acc[mi][ni][1] = acc[mi][ni][2] = acc[mi][ni][3] = 0.f;

    #pragma unroll
    for (int ks = 0; ks < 16; ks++) {
        int k0 = ks * 8;
        unsigned a[2][4], bf[4][2];
        #pragma unroll
        for (int mi = 0; mi < 2; mi++) {
            int r = wm*32 + mi*16 + lr;
            a[mi][0] = fu(As[r*132 + k0 + lc]);
            a[mi][1] = fu(As[(r+8)*132 + k0 + lc]);
            a[mi][2] = fu(As[r*132 + k0 + 4 + lc]);
            a[mi][3] = fu(As[(r+8)*132 + k0 + 4 + lc]);
        }
        #pragma unroll
        for (int ni = 0; ni < 4; ni++) {
            int n = wn*32 + ni*8 + lr;
            bf[ni][0] = fu(Bs[(k0 + lc)*132 + n]);
            bf[ni][1] = fu(Bs[(k0 + 4 + lc)*132 + n]);
        }
        #pragma unroll
        for (int mi = 0; mi < 2; mi++)
            #pragma unroll
            for (int ni = 0; ni < 4; ni++)
                mma_tf32(acc[mi][ni], a[mi], bf[ni]);
    }

    #pragma unroll
    for (int mi = 0; mi < 2; mi++) {
        #pragma unroll
        for (int ni = 0; ni < 4; ni++) {
            int gr = m0 + wm*32 + mi*16 + lr;
            int cn = wn*32 + ni*8 + lc*2;
            float b0 = bout[cn], b1 = bout[cn+1];
            out[(size_t)gr * CDIM + cn]           = acc[mi][ni][0] + b0;
            out[(size_t)gr * CDIM + cn + 1]       = acc[mi][ni][1] + b1;
            out[(size_t)(gr+8) * CDIM + cn]       = acc[mi][ni][2] + b0;
            out[(size_t)(gr+8) * CDIM + cn + 1]   = acc[mi][ni][3] + b1;
        }
    }
}

// ---------------- launch ----------------
extern "C" void kernel_launch(void* const* d_in, const int* in_sizes, int n_in,
                              void* d_out, int out_size)
{
    (void)in_sizes; (void)n_in; (void)out_size;
    const float* z        = (const float*)d_in[0];
    const int*   src_mask = (const int*)  d_in[1];
    const float* ln_g     = (const float*)d_in[2];
    const float* ln_b     = (const float*)d_in[3];
    const float* w_qkv    = (const float*)d_in[4];
    const float* w_pair   = (const float*)d_in[5];
    const float* w_gate   = (const float*)d_in[6];
    const float* b_gate   = (const float*)d_in[7];
    const float* w_out    = (const float*)d_in[8];
    const float* b_out    = (const float*)d_in[9];
    float* out = (float*)d_out;

    const int qkv_smem = GEMM_QKV_SMEM_FLOATS * 4;   // 138240
    const int out_smem = GEMM_OUT_SMEM_FLOATS * 4;   // 135168
    const int attn_smem = ATTN_SMEM_FLOATS * 4;      // 93184
    cudaFuncSetAttribute(gemm_qkv_gate,   cudaFuncAttributeMaxDynamicSharedMemorySize, qkv_smem);
    cudaFuncSetAttribute(attn_kernel,     cudaFuncAttributeMaxDynamicSharedMemorySize, attn_smem);
    cudaFuncSetAttribute(gemm_out_kernel, cudaFuncAttributeMaxDynamicSharedMemorySize, out_smem);

    gemm_qkv_gate<<<dim3(NROWS/128, 4), 512, qkv_smem>>>(z, ln_g, ln_b, w_qkv, w_gate, b_gate, w_pair);
    attn_kernel<<<dim3(NH, LDIM), 256, attn_smem>>>(src_mask);
    gemm_out_kernel<<<NROWS/128, 512, out_smem>>>(w_out, b_out, out);
}